// round 1
// baseline (speedup 1.0000x reference)
#include <cuda_runtime.h>
#include <math.h>

// Problem constants
#define PB   2
#define PS   2048
#define PHID 2048
#define PH   16
#define PD   128
#define PM   (PB * PS)          // 4096 rows
#define QSCALE 11.313708498984760f   // sqrt(128)

// Scratch (no cudaMalloc allowed)
__device__ float g_q[(size_t)PM * PHID];
__device__ float g_k[(size_t)PM * PHID];
__device__ float g_v[(size_t)PM * PHID];
__device__ float g_ctx[(size_t)PM * PHID];

// ---------------------------------------------------------------------------
// SGEMM: C[M,N] = (A[M,K] @ W[K,N] + bias[N]) * scale      (row-major, fp32)
// 128x128 tile, BK=16, 256 threads, 8x8 per thread.
// ---------------------------------------------------------------------------
__global__ __launch_bounds__(256) void sgemm_bias(
    const float* __restrict__ A, const float* __restrict__ W,
    const float* __restrict__ bias, float* __restrict__ C,
    int M, int N, int K, float scale)
{
    __shared__ float As[16][132];   // transposed A tile: As[k][m]
    __shared__ float Bs[16][128];   // Bs[k][n]

    int tid = threadIdx.x;
    int m0 = blockIdx.y * 128;
    int n0 = blockIdx.x * 128;
    int ty = tid >> 4;          // 0..15
    int tx = tid & 15;          // 0..15

    int arow = tid >> 2;        // 0..63
    int acol = (tid & 3) << 2;  // 0,4,8,12
    int brow = tid >> 5;        // 0..7
    int bcol = (tid & 31) << 2; // 0..124

    float acc[8][8];
#pragma unroll
    for (int i = 0; i < 8; i++)
#pragma unroll
        for (int j = 0; j < 8; j++) acc[i][j] = 0.0f;

    const float* Ap0 = A + (size_t)(m0 + arow) * K + acol;
    const float* Ap1 = A + (size_t)(m0 + arow + 64) * K + acol;

    for (int k0 = 0; k0 < K; k0 += 16) {
        float4 a0 = *(const float4*)(Ap0 + k0);
        float4 a1 = *(const float4*)(Ap1 + k0);
        float4 b0 = *(const float4*)(W + (size_t)(k0 + brow) * N + n0 + bcol);
        float4 b1 = *(const float4*)(W + (size_t)(k0 + brow + 8) * N + n0 + bcol);

        As[acol + 0][arow] = a0.x;
        As[acol + 1][arow] = a0.y;
        As[acol + 2][arow] = a0.z;
        As[acol + 3][arow] = a0.w;
        As[acol + 0][arow + 64] = a1.x;
        As[acol + 1][arow + 64] = a1.y;
        As[acol + 2][arow + 64] = a1.z;
        As[acol + 3][arow + 64] = a1.w;
        *(float4*)&Bs[brow][bcol]     = b0;
        *(float4*)&Bs[brow + 8][bcol] = b1;
        __syncthreads();

#pragma unroll
        for (int kk = 0; kk < 16; kk++) {
            float4 av0 = *(const float4*)&As[kk][ty * 8];
            float4 av1 = *(const float4*)&As[kk][ty * 8 + 4];
            float4 bv0 = *(const float4*)&Bs[kk][tx * 8];
            float4 bv1 = *(const float4*)&Bs[kk][tx * 8 + 4];
            float a8[8] = {av0.x, av0.y, av0.z, av0.w, av1.x, av1.y, av1.z, av1.w};
            float b8[8] = {bv0.x, bv0.y, bv0.z, bv0.w, bv1.x, bv1.y, bv1.z, bv1.w};
#pragma unroll
            for (int i = 0; i < 8; i++)
#pragma unroll
                for (int j = 0; j < 8; j++)
                    acc[i][j] += a8[i] * b8[j];
        }
        __syncthreads();
    }

    float4 bia0 = *(const float4*)(bias + n0 + tx * 8);
    float4 bia1 = *(const float4*)(bias + n0 + tx * 8 + 4);
    float bi[8] = {bia0.x, bia0.y, bia0.z, bia0.w, bia1.x, bia1.y, bia1.z, bia1.w};
#pragma unroll
    for (int i = 0; i < 8; i++) {
        size_t row = (size_t)(m0 + ty * 8 + i);
        float out8[8];
#pragma unroll
        for (int j = 0; j < 8; j++) out8[j] = (acc[i][j] + bi[j]) * scale;
        float4 o0 = make_float4(out8[0], out8[1], out8[2], out8[3]);
        float4 o1 = make_float4(out8[4], out8[5], out8[6], out8[7]);
        *(float4*)(C + row * N + n0 + tx * 8)     = o0;
        *(float4*)(C + row * N + n0 + tx * 8 + 4) = o1;
    }
}

// ---------------------------------------------------------------------------
// Flash-style attention, fp32.
// Block: one (b,h), 64 query rows.  Loops over 64-row K/V tiles with online
// softmax.  Q is pre-scaled by sqrt(D) in the projection GEMM.
// smem: qT[128][72], kT[128][72], v[64][132], p[64][68]  = 124,928 B
// Threads: 256.  Score phase: thread(ty,tx) -> rows ty*4..+4, cols tx*4..+4.
// PV phase:     thread(ty,tx) -> rows ty*4..+4, d cols tx*8..+8.
// ---------------------------------------------------------------------------
#define ATTN_SMEM_FLOATS (128 * 72 * 2 + 64 * 132 + 64 * 68)

__global__ __launch_bounds__(256) void attn_kernel(
    const float* __restrict__ Qg, const float* __restrict__ Kg,
    const float* __restrict__ Vg, const float* __restrict__ Bias,
    float* __restrict__ Ctx)
{
    extern __shared__ float sm[];
    float* qT = sm;                    // [128][72]  (d-major, row minor)
    float* kT = qT + 128 * 72;         // [128][72]
    float* vs = kT + 128 * 72;         // [64][132]
    float* ps = vs + 64 * 132;         // [64][68]

    int tid = threadIdx.x;
    int ty = tid >> 4;                 // 0..15
    int tx = tid & 15;                 // 0..15
    int ty4 = ty * 4, tx4 = tx * 4, tx8 = tx * 8;

    int bh = blockIdx.y;               // 0..31
    int b  = bh >> 4;
    int h  = bh & 15;
    int q0 = blockIdx.x * 64;

    const float* qbase = Qg + (size_t)b * PS * PHID + h * PD;
    const float* kbase = Kg + (size_t)b * PS * PHID + h * PD;
    const float* vbase = Vg + (size_t)b * PS * PHID + h * PD;
    const float* biasbase = Bias + ((size_t)bh * PS + q0) * PS;

    // Load Q tile transposed into smem
    for (int idx = tid; idx < 64 * 32; idx += 256) {
        int r = idx >> 5;
        int d = (idx & 31) << 2;
        float4 t = *(const float4*)(qbase + (size_t)(q0 + r) * PHID + d);
        qT[(d + 0) * 72 + r] = t.x;
        qT[(d + 1) * 72 + r] = t.y;
        qT[(d + 2) * 72 + r] = t.z;
        qT[(d + 3) * 72 + r] = t.w;
    }

    float m_r[4], l_r[4], o[4][8];
#pragma unroll
    for (int i = 0; i < 4; i++) {
        m_r[i] = -1e30f;
        l_r[i] = 0.0f;
#pragma unroll
        for (int d = 0; d < 8; d++) o[i][d] = 0.0f;
    }

    for (int k0 = 0; k0 < PS; k0 += 64) {
        __syncthreads();   // prior-iteration consumers done (and qT ready, iter 0)

        // Load K tile (transposed) and V tile
        for (int idx = tid; idx < 64 * 32; idx += 256) {
            int r = idx >> 5;
            int d = (idx & 31) << 2;
            float4 t = *(const float4*)(kbase + (size_t)(k0 + r) * PHID + d);
            kT[(d + 0) * 72 + r] = t.x;
            kT[(d + 1) * 72 + r] = t.y;
            kT[(d + 2) * 72 + r] = t.z;
            kT[(d + 3) * 72 + r] = t.w;
            float4 u = *(const float4*)(vbase + (size_t)(k0 + r) * PHID + d);
            *(float4*)&vs[r * 132 + d] = u;
        }
        __syncthreads();

        // Scores: s = q·k + bias   (q pre-scaled)
        float s[4][4];
#pragma unroll
        for (int i = 0; i < 4; i++) {
            float4 bb = *(const float4*)(biasbase + (size_t)(ty4 + i) * PS + k0 + tx4);
            s[i][0] = bb.x; s[i][1] = bb.y; s[i][2] = bb.z; s[i][3] = bb.w;
        }
#pragma unroll 8
        for (int kk = 0; kk < 128; kk++) {
            float4 a  = *(const float4*)&qT[kk * 72 + ty4];
            float4 bb = *(const float4*)&kT[kk * 72 + tx4];
            float av[4] = {a.x, a.y, a.z, a.w};
            float bv[4] = {bb.x, bb.y, bb.z, bb.w};
#pragma unroll
            for (int i = 0; i < 4; i++)
#pragma unroll
                for (int j = 0; j < 4; j++)
                    s[i][j] += av[i] * bv[j];
        }

        // Online softmax update (rows shared by 16 lanes of a half-warp)
        float alpha[4];
#pragma unroll
        for (int i = 0; i < 4; i++) {
            float mx = fmaxf(fmaxf(s[i][0], s[i][1]), fmaxf(s[i][2], s[i][3]));
#pragma unroll
            for (int off = 8; off >= 1; off >>= 1)
                mx = fmaxf(mx, __shfl_xor_sync(0xffffffffu, mx, off));
            float mnew = fmaxf(m_r[i], mx);
            alpha[i] = __expf(m_r[i] - mnew);
            m_r[i] = mnew;
            float lsum = 0.0f;
#pragma unroll
            for (int j = 0; j < 4; j++) {
                s[i][j] = __expf(s[i][j] - mnew);
                lsum += s[i][j];
            }
#pragma unroll
            for (int off = 8; off >= 1; off >>= 1)
                lsum += __shfl_xor_sync(0xffffffffu, lsum, off);
            l_r[i] = l_r[i] * alpha[i] + lsum;
            *(float4*)&ps[(ty4 + i) * 68 + tx4] =
                make_float4(s[i][0], s[i][1], s[i][2], s[i][3]);
        }
        __syncthreads();

#pragma unroll
        for (int i = 0; i < 4; i++)
#pragma unroll
            for (int d = 0; d < 8; d++) o[i][d] *= alpha[i];

        // O += P @ V
#pragma unroll 2
        for (int j = 0; j < 64; j += 4) {
            float pr[4][4];
#pragma unroll
            for (int i = 0; i < 4; i++) {
                float4 t = *(const float4*)&ps[(ty4 + i) * 68 + j];
                pr[i][0] = t.x; pr[i][1] = t.y; pr[i][2] = t.z; pr[i][3] = t.w;
            }
#pragma unroll
            for (int jj = 0; jj < 4; jj++) {
                float4 va = *(const float4*)&vs[(j + jj) * 132 + tx8];
                float4 vb = *(const float4*)&vs[(j + jj) * 132 + tx8 + 4];
                float v8[8] = {va.x, va.y, va.z, va.w, vb.x, vb.y, vb.z, vb.w};
#pragma unroll
                for (int i = 0; i < 4; i++) {
                    float p = pr[i][jj];
#pragma unroll
                    for (int d = 0; d < 8; d++) o[i][d] += p * v8[d];
                }
            }
        }
    }

    // Normalize and write ctx[b, q, h, d]
#pragma unroll
    for (int i = 0; i < 4; i++) {
        float inv = 1.0f / l_r[i];
        size_t row = (size_t)b * PS + q0 + ty4 + i;
        float* dst = Ctx + row * PHID + h * PD + tx8;
        float4 o0 = make_float4(o[i][0] * inv, o[i][1] * inv, o[i][2] * inv, o[i][3] * inv);
        float4 o1 = make_float4(o[i][4] * inv, o[i][5] * inv, o[i][6] * inv, o[i][7] * inv);
        *(float4*)dst       = o0;
        *(float4*)(dst + 4) = o1;
    }
}

// ---------------------------------------------------------------------------
extern "C" void kernel_launch(void* const* d_in, const int* in_sizes, int n_in,
                              void* d_out, int out_size)
{
    (void)in_sizes; (void)n_in; (void)out_size;
    const float* x    = (const float*)d_in[0];
    const float* bias = (const float*)d_in[1];
    const float* Wq   = (const float*)d_in[2];
    const float* bq   = (const float*)d_in[3];
    const float* Wk   = (const float*)d_in[4];
    const float* bk   = (const float*)d_in[5];
    const float* Wv   = (const float*)d_in[6];
    const float* bv   = (const float*)d_in[7];
    const float* Wo   = (const float*)d_in[8];
    const float* bo   = (const float*)d_in[9];
    float* out = (float*)d_out;

    float *q, *k, *v, *ctx;
    cudaGetSymbolAddress((void**)&q,   g_q);
    cudaGetSymbolAddress((void**)&k,   g_k);
    cudaGetSymbolAddress((void**)&v,   g_v);
    cudaGetSymbolAddress((void**)&ctx, g_ctx);

    static bool attr_set = false;
    if (!attr_set) {
        cudaFuncSetAttribute(attn_kernel,
                             cudaFuncAttributeMaxDynamicSharedMemorySize,
                             ATTN_SMEM_FLOATS * (int)sizeof(float));
        attr_set = true;
    }

    dim3 ggrid(PHID / 128, PM / 128);   // (16, 32)
    sgemm_bias<<<ggrid, 256>>>(x, Wq, bq, q, PM, PHID, PHID, QSCALE);
    sgemm_bias<<<ggrid, 256>>>(x, Wk, bk, k, PM, PHID, PHID, 1.0f);
    sgemm_bias<<<ggrid, 256>>>(x, Wv, bv, v, PM, PHID, PHID, 1.0f);

    dim3 agrid(PS / 64, PB * PH);       // (32, 32)
    attn_kernel<<<agrid, 256, ATTN_SMEM_FLOATS * sizeof(float)>>>(q, k, v, bias, ctx);

    sgemm_bias<<<ggrid, 256>>>(ctx, Wo, bo, out, PM, PHID, PHID, 1.0f);
}